// round 14
// baseline (speedup 1.0000x reference)
#include <cuda_runtime.h>
#include <cuda_fp16.h>
#include <math.h>
#include <cstdint>

#define CN 8192
#define CD 128
#define CV 3

#define TM 128            // n rows per CTA tile
#define TN 64             // m cols per tile
#define NTILES (CN / TM)  // 64
#define MTILES (CN / TN)  // 128
#define TOTAL_JOBS (NTILES * MTILES)  // 8192
#define TOTROWS ((CV + 1) * CN)       // 32768

#define RSTRIDE 272       // padded row stride (bytes): conflict-free ldmatrix
#define A_OFF 0
#define A_BYTES (TM * RSTRIDE)                 // 34816
#define B_OFF A_BYTES
#define B_VIEW_BYTES (TN * RSTRIDE)            // 17408
#define B_BUF_BYTES (CV * B_VIEW_BYTES)        // 52224
#define NBUF 3
#define SMEM_TOTAL (B_OFF + NBUF * B_BUF_BYTES)  // 191488

#define K2LOG2E 2.8853900817779268f  /* 2/ln2 : exp(2*sim) = 2^(sim*K2) */
#define LN2F 0.6931471805599453f

// ---- device scratch ----
__device__ __align__(256) __half g_Hc16[CN * CD];   // pre-scaled by 2/ln2
__device__ __align__(256) __half g_Hv16[CV * CN * CD];
__device__ __align__(256) float g_denom[CV * CN];
__device__ __align__(256) float g_pos[CV * CN];     // positives (diag), written by main
__device__ unsigned int g_done;

// ---------------- helpers ----------------
__device__ __forceinline__ uint32_t smem_u32(const void* p) {
    uint32_t a;
    asm("{ .reg .u64 t; cvta.to.shared.u64 t, %1; cvt.u32.u64 %0, t; }" : "=r"(a) : "l"(p));
    return a;
}
__device__ __forceinline__ void cp_async16(uint32_t dst, const void* src) {
    asm volatile("cp.async.cg.shared.global [%0], [%1], 16;" :: "r"(dst), "l"(src));
}
#define CP_COMMIT() asm volatile("cp.async.commit_group;" ::: "memory")
#define CP_WAIT0()  asm volatile("cp.async.wait_group 0;" ::: "memory")
#define CP_WAIT1()  asm volatile("cp.async.wait_group 1;" ::: "memory")

__device__ __forceinline__ void ldm4(uint32_t* r, uint32_t a) {
    asm volatile("ldmatrix.sync.aligned.m8n8.x4.shared.b16 {%0,%1,%2,%3}, [%4];"
                 : "=r"(r[0]), "=r"(r[1]), "=r"(r[2]), "=r"(r[3]) : "r"(a));
}
__device__ __forceinline__ void mma16816h(uint32_t* c, const uint32_t* a, uint32_t b0, uint32_t b1) {
    asm volatile(
        "mma.sync.aligned.m16n8k16.row.col.f16.f16.f16.f16 "
        "{%0,%1}, {%2,%3,%4,%5}, {%6,%7}, {%0,%1};"
        : "+r"(c[0]), "+r"(c[1])
        : "r"(a[0]), "r"(a[1]), "r"(a[2]), "r"(a[3]), "r"(b0), "r"(b1));
}
__device__ __forceinline__ __half2 ex2h2(uint32_t x) {
    uint32_t r;
    asm("ex2.approx.f16x2 %0, %1;" : "=r"(r) : "r"(x));
    return *reinterpret_cast<__half2*>(&r);
}

// ---- kernel 1: L2-normalize, 2 rows per warp, rsqrt fast path, fused zeroing ----
// 256 threads = 8 warps x 2 rows = 16 rows/block; grid = TOTROWS/16 = 2048
__global__ __launch_bounds__(256) void sg_normalize_kernel(const float* __restrict__ Hc,
                                                           const float* __restrict__ Hv) {
    if (blockIdx.x < (CV * CN) / 256) {
        g_denom[blockIdx.x * 256 + threadIdx.x] = 0.0f;
        if (blockIdx.x == 0 && threadIdx.x == 0) g_done = 0u;
    }

    const int wid = threadIdx.x >> 5;
    const int lane = threadIdx.x & 31;
    const int row0 = blockIdx.x * 16 + wid * 2;
    const int row1 = row0 + 1;

    const float* src0; __half* dst0; float sc0;
    const float* src1; __half* dst1; float sc1;
    if (row0 < CN) { src0 = Hc + (size_t)row0 * CD; dst0 = g_Hc16 + (size_t)row0 * CD; sc0 = K2LOG2E; }
    else { src0 = Hv + (size_t)(row0 - CN) * CD; dst0 = g_Hv16 + (size_t)(row0 - CN) * CD; sc0 = 1.0f; }
    if (row1 < CN) { src1 = Hc + (size_t)row1 * CD; dst1 = g_Hc16 + (size_t)row1 * CD; sc1 = K2LOG2E; }
    else { src1 = Hv + (size_t)(row1 - CN) * CD; dst1 = g_Hv16 + (size_t)(row1 - CN) * CD; sc1 = 1.0f; }

    float4 x0 = reinterpret_cast<const float4*>(src0)[lane];
    float4 x1 = reinterpret_cast<const float4*>(src1)[lane];
    float s0 = x0.x * x0.x + x0.y * x0.y + x0.z * x0.z + x0.w * x0.w;
    float s1 = x1.x * x1.x + x1.y * x1.y + x1.z * x1.z + x1.w * x1.w;
#pragma unroll
    for (int o = 16; o > 0; o >>= 1) {
        s0 += __shfl_xor_sync(0xffffffffu, s0, o);
        s1 += __shfl_xor_sync(0xffffffffu, s1, o);
    }
    float i0 = sc0 * rsqrtf(fmaxf(s0, 1e-24f));
    float i1 = sc1 * rsqrtf(fmaxf(s1, 1e-24f));
    {
        __half2 h0 = __floats2half2_rn(x0.x * i0, x0.y * i0);
        __half2 h1 = __floats2half2_rn(x0.z * i0, x0.w * i0);
        uint2 u; u.x = *reinterpret_cast<uint32_t*>(&h0); u.y = *reinterpret_cast<uint32_t*>(&h1);
        reinterpret_cast<uint2*>(dst0)[lane] = u;
    }
    {
        __half2 h0 = __floats2half2_rn(x1.x * i1, x1.y * i1);
        __half2 h1 = __floats2half2_rn(x1.z * i1, x1.w * i1);
        uint2 u; u.x = *reinterpret_cast<uint32_t*>(&h0); u.y = *reinterpret_cast<uint32_t*>(&h1);
        reinterpret_cast<uint2*>(dst1)[lane] = u;
    }
}

// ---- smem tile loaders ----
__device__ __forceinline__ void load_A(uint32_t sb, int n0, int t) {
#pragma unroll
    for (int k = 0; k < 8; k++) {
        int q = t + k * 256;
        int r = q >> 4;
        int c = q & 15;
        cp_async16(sb + A_OFF + r * RSTRIDE + c * 16,
                   g_Hc16 + (size_t)(n0 + r) * CD + c * 8);
    }
}
__device__ __forceinline__ void load_B(uint32_t sb, int buf, int m0, int t) {
    uint32_t base = sb + B_OFF + buf * B_BUF_BYTES;
#pragma unroll
    for (int k = 0; k < 12; k++) {
        int Q = t + k * 256;
        int v = Q >> 10;
        int qq = Q & 1023;
        int r = qq >> 4;
        int c = qq & 15;
        cp_async16(base + v * B_VIEW_BYTES + r * RSTRIDE + c * 16,
                   g_Hv16 + ((size_t)v * CN + (m0 + r)) * CD + c * 8);
    }
}

// ---- kernel 2: HMMA(f16-acc) fused GEMM + exp + denom + diag positives + final reduce ----
__global__ __launch_bounds__(256, 1) void sg_main_kernel(const float* __restrict__ S,
                                                         float* __restrict__ out) {
    // PDL: grid may launch while normalize is still draining; wait before reading
    cudaGridDependencySynchronize();

    extern __shared__ char smem[];
    uint32_t sb = smem_u32(smem);
    const int t = threadIdx.x;
    const int lane = t & 31;
    const int wid = t >> 5;
    const int wn = wid >> 1;     // 0..3 : n quarter
    const int wm = wid & 1;      // 0..1 : m half
    const int g = lane >> 3;
    const int lr = lane & 7;
    const uint32_t aoff = (uint32_t)(((g & 1) * 8 + lr) * RSTRIDE + (g >> 1) * 16);
    const uint32_t boff = (uint32_t)(((g >> 1) * 8 + lr) * RSTRIDE + (g & 1) * 16);

    const int job0 = (int)(((long long)blockIdx.x * TOTAL_JOBS) / gridDim.x);
    const int job1 = (int)(((long long)(blockIdx.x + 1) * TOTAL_JOBS) / gridDim.x);

    int j = job0;
    while (j < job1) {
        const int nt = j >> 7;
        const int mt0 = j & 127;
        const int jend = min(job1, (nt + 1) << 7);
        const int nTi = jend - j;
        const int n0 = nt * TM;

        __syncthreads();  // previous segment fully done before overwriting smem
        load_A(sb, n0, t);
        load_B(sb, 0, mt0 * TN, t);
        CP_COMMIT();
        if (nTi > 1) { load_B(sb, 1, (mt0 + 1) * TN, t); }
        CP_COMMIT();

        uint32_t af[8][2][4];
        float denomAcc[CV][2][2];
#pragma unroll
        for (int v = 0; v < CV; v++)
#pragma unroll
            for (int a = 0; a < 2; a++)
#pragma unroll
                for (int b = 0; b < 2; b++) denomAcc[v][a][b] = 0.0f;

        const int row_base = n0 + wn * 32 + (lane >> 2);
        const int col_base = wm * 32 + 2 * (lane & 3);

        int buf = 0;
        for (int i = 0; i < nTi; i++) {
            if (i + 1 < nTi) CP_WAIT1(); else CP_WAIT0();
            __syncthreads();  // B(i) visible; compute(i-1) done everywhere

            int nbuf = buf + 2; if (nbuf >= 3) nbuf -= 3;
            if (i + 2 < nTi) { load_B(sb, nbuf, (mt0 + i + 2) * TN, t); CP_COMMIT(); }

            if (i == 0) {
                uint32_t abase = sb + A_OFF + (uint32_t)(wn * 32) * RSTRIDE + aoff;
#pragma unroll
                for (int ks = 0; ks < 8; ks++)
#pragma unroll
                    for (int mi = 0; mi < 2; mi++)
                        ldm4(af[ks][mi], abase + mi * 16 * RSTRIDE + ks * 32);
            }

            const int mt = mt0 + i;
            const int m0 = mt * TN;
            const bool diag = ((mt >> 1) == nt);   // tile contains sim diagonal
            __half2 wv[2][2][4];  // [mi][row-octet][ni]
#pragma unroll
            for (int mi = 0; mi < 2; mi++)
#pragma unroll
                for (int d8 = 0; d8 < 2; d8++) {
                    const float* rp = S + (size_t)(row_base + mi * 16 + 8 * d8) * CN +
                                      (m0 + col_base);
#pragma unroll
                    for (int ni = 0; ni < 4; ni++) {
                        float2 x = *reinterpret_cast<const float2*>(rp + ni * 8);
                        wv[mi][d8][ni] = __floats2half2_rn(1.0f - x.x, 1.0f - x.y);
                    }
                }

#pragma unroll
            for (int v = 0; v < CV; v++) {
                uint32_t acc[2][4][2];
#pragma unroll
                for (int mi = 0; mi < 2; mi++)
#pragma unroll
                    for (int ni = 0; ni < 4; ni++) {
                        acc[mi][ni][0] = 0u; acc[mi][ni][1] = 0u;
                    }

                uint32_t bbase = sb + B_OFF + buf * B_BUF_BYTES + v * B_VIEW_BYTES +
                                 (uint32_t)(wm * 32) * RSTRIDE + boff;
#pragma unroll
                for (int ks = 0; ks < 8; ks++) {
                    uint32_t bf0[4], bf1[4];
                    ldm4(bf0, bbase + ks * 32);
                    ldm4(bf1, bbase + 16 * RSTRIDE + ks * 32);
#pragma unroll
                    for (int mi = 0; mi < 2; mi++) {
                        mma16816h(acc[mi][0], af[ks][mi], bf0[0], bf0[1]);
                        mma16816h(acc[mi][1], af[ks][mi], bf0[2], bf0[3]);
                        mma16816h(acc[mi][2], af[ks][mi], bf1[0], bf1[1]);
                        mma16816h(acc[mi][3], af[ks][mi], bf1[2], bf1[3]);
                    }
                }

                if (diag) {
                    // extract positives: unique owner per diagonal element
#pragma unroll
                    for (int mi = 0; mi < 2; mi++)
#pragma unroll
                        for (int ni = 0; ni < 4; ni++)
#pragma unroll
                            for (int oct = 0; oct < 2; oct++) {
                                int row = row_base + mi * 16 + 8 * oct;
                                int col = m0 + col_base + ni * 8;
                                __half2 h = *reinterpret_cast<__half2*>(&acc[mi][ni][oct]);
                                if (row == col)
                                    g_pos[v * CN + row] = __half2float(h.x) * LN2F;
                                else if (row == col + 1)
                                    g_pos[v * CN + row] = __half2float(h.y) * LN2F;
                            }
                }

#pragma unroll
                for (int mi = 0; mi < 2; mi++) {
                    __half2 h0 = __floats2half2_rn(0.0f, 0.0f);
                    __half2 h1 = h0;
#pragma unroll
                    for (int ni = 0; ni < 4; ni++) {
                        h0 = __hfma2(wv[mi][0][ni], ex2h2(acc[mi][ni][0]), h0);
                        h1 = __hfma2(wv[mi][1][ni], ex2h2(acc[mi][ni][1]), h1);
                    }
                    float2 f0 = __half22float2(h0);
                    float2 f1 = __half22float2(h1);
                    denomAcc[v][mi][0] += f0.x + f0.y;
                    denomAcc[v][mi][1] += f1.x + f1.y;
                }
            }
            buf++; if (buf >= 3) buf -= 3;
        }

#pragma unroll
        for (int v = 0; v < CV; v++)
#pragma unroll
            for (int mi = 0; mi < 2; mi++)
#pragma unroll
                for (int d8 = 0; d8 < 2; d8++) {
                    float val = denomAcc[v][mi][d8];
                    val += __shfl_xor_sync(0xffffffffu, val, 1);
                    val += __shfl_xor_sync(0xffffffffu, val, 2);
                    if ((lane & 3) == 0)
                        atomicAdd(&g_denom[v * CN + row_base + mi * 16 + 8 * d8], val);
                }
        j = jend;
    }

    // ---- fused finalize: last CTA to finish reduces the loss and writes out ----
    __threadfence();
    __syncthreads();
    __shared__ bool isLast;
    if (t == 0) {
        unsigned int d = atomicAdd(&g_done, 1u);
        isLast = (d == gridDim.x - 1);
    }
    __syncthreads();
    if (isLast) {
        // all other CTAs' denom/pos writes are globally visible (fence-before-atomic)
        float local = 0.0f;
#pragma unroll 4
        for (int i = t; i < CV * CN; i += 256) {
            float den = fmaxf(g_denom[i], 1e-9f);
            local += __logf(den) - g_pos[i];
        }
#pragma unroll
        for (int o = 16; o > 0; o >>= 1) local += __shfl_xor_sync(0xffffffffu, local, o);
        __shared__ double part[8];
        if (lane == 0) part[wid] = (double)local;
        __syncthreads();
        if (t == 0) {
            double bs = 0.0;
#pragma unroll
            for (int w = 0; w < 8; w++) bs += part[w];
            out[0] = (float)(bs / (double)((long long)CN * CV));
            g_done = 0u;   // reset for next graph replay
        }
    }
}

extern "C" void kernel_launch(void* const* d_in, const int* in_sizes, int n_in,
                              void* d_out, int out_size) {
    const float* Hc = (const float*)d_in[0];
    const float* S = (const float*)d_in[1];
    const float* Hv = (const float*)d_in[2];
    float* out = (float*)d_out;

    int nsm = 148;
    cudaDeviceGetAttribute(&nsm, cudaDevAttrMultiProcessorCount, 0);

    cudaFuncSetAttribute(sg_main_kernel, cudaFuncAttributeMaxDynamicSharedMemorySize,
                         SMEM_TOTAL);

    // kernel 1: plain launch
    sg_normalize_kernel<<<TOTROWS / 16, 256>>>(Hc, Hv);

    // kernel 2: PDL — overlap grid launch with normalize tail; finalize fused inside
    {
        cudaLaunchConfig_t cfg = {};
        cfg.gridDim = dim3((unsigned)nsm, 1, 1);
        cfg.blockDim = dim3(256, 1, 1);
        cfg.dynamicSmemBytes = SMEM_TOTAL;
        cfg.stream = 0;
        cudaLaunchAttribute attr[1];
        attr[0].id = cudaLaunchAttributeProgrammaticStreamSerialization;
        attr[0].val.programmaticStreamSerializationAllowed = 1;
        cfg.attrs = attr;
        cfg.numAttrs = 1;
        cudaLaunchKernelEx(&cfg, sg_main_kernel, S, out);
    }
}

// round 15
// speedup vs baseline: 1.0384x; 1.0384x over previous
#include <cuda_runtime.h>
#include <cuda_fp16.h>
#include <math.h>
#include <cstdint>

#define CN 8192
#define CD 128
#define CV 3

#define TM 128            // n rows per CTA tile
#define TN 64             // m cols per tile
#define NTILES (CN / TM)  // 64
#define MTILES (CN / TN)  // 128
#define TOTAL_JOBS (NTILES * MTILES)  // 8192
#define TOTROWS ((CV + 1) * CN)       // 32768

#define NTHREADS 512

#define RSTRIDE 272       // padded row stride (bytes): conflict-free ldmatrix
#define A_OFF 0
#define A_BYTES (TM * RSTRIDE)                 // 34816
#define B_OFF A_BYTES
#define B_VIEW_BYTES (TN * RSTRIDE)            // 17408
#define B_BUF_BYTES (CV * B_VIEW_BYTES)        // 52224
#define NBUF 3
#define SMEM_TOTAL (B_OFF + NBUF * B_BUF_BYTES)  // 191488

#define K2LOG2E 2.8853900817779268f  /* 2/ln2 : exp(2*sim) = 2^(sim*K2) */
#define LN2F 0.6931471805599453f

// ---- device scratch ----
__device__ __align__(256) __half g_Hc16[CN * CD];   // pre-scaled by 2/ln2
__device__ __align__(256) __half g_Hv16[CV * CN * CD];
__device__ __align__(256) float g_denom[CV * CN];
__device__ __align__(256) float g_pos[CV * CN];     // positives (diag), written by main
__device__ double g_loss;
__device__ unsigned int g_done;

// ---------------- helpers ----------------
__device__ __forceinline__ uint32_t smem_u32(const void* p) {
    uint32_t a;
    asm("{ .reg .u64 t; cvta.to.shared.u64 t, %1; cvt.u32.u64 %0, t; }" : "=r"(a) : "l"(p));
    return a;
}
__device__ __forceinline__ void cp_async16(uint32_t dst, const void* src) {
    asm volatile("cp.async.cg.shared.global [%0], [%1], 16;" :: "r"(dst), "l"(src));
}
#define CP_COMMIT() asm volatile("cp.async.commit_group;" ::: "memory")
#define CP_WAIT0()  asm volatile("cp.async.wait_group 0;" ::: "memory")
#define CP_WAIT1()  asm volatile("cp.async.wait_group 1;" ::: "memory")

__device__ __forceinline__ void ldm4(uint32_t* r, uint32_t a) {
    asm volatile("ldmatrix.sync.aligned.m8n8.x4.shared.b16 {%0,%1,%2,%3}, [%4];"
                 : "=r"(r[0]), "=r"(r[1]), "=r"(r[2]), "=r"(r[3]) : "r"(a));
}
__device__ __forceinline__ void mma16816h(uint32_t* c, const uint32_t* a, uint32_t b0, uint32_t b1) {
    asm volatile(
        "mma.sync.aligned.m16n8k16.row.col.f16.f16.f16.f16 "
        "{%0,%1}, {%2,%3,%4,%5}, {%6,%7}, {%0,%1};"
        : "+r"(c[0]), "+r"(c[1])
        : "r"(a[0]), "r"(a[1]), "r"(a[2]), "r"(a[3]), "r"(b0), "r"(b1));
}
__device__ __forceinline__ __half2 ex2h2(uint32_t x) {
    uint32_t r;
    asm("ex2.approx.f16x2 %0, %1;" : "=r"(r) : "r"(x));
    return *reinterpret_cast<__half2*>(&r);
}

// ---- kernel 1: L2-normalize, 2 rows per warp, rsqrt fast path, fused zeroing ----
__global__ __launch_bounds__(256) void sg_normalize_kernel(const float* __restrict__ Hc,
                                                           const float* __restrict__ Hv) {
    if (blockIdx.x < (CV * CN) / 256) {
        g_denom[blockIdx.x * 256 + threadIdx.x] = 0.0f;
        if (blockIdx.x == 0 && threadIdx.x == 0) { g_loss = 0.0; g_done = 0u; }
    }

    const int wid = threadIdx.x >> 5;
    const int lane = threadIdx.x & 31;
    const int row0 = blockIdx.x * 16 + wid * 2;
    const int row1 = row0 + 1;

    const float* src0; __half* dst0; float sc0;
    const float* src1; __half* dst1; float sc1;
    if (row0 < CN) { src0 = Hc + (size_t)row0 * CD; dst0 = g_Hc16 + (size_t)row0 * CD; sc0 = K2LOG2E; }
    else { src0 = Hv + (size_t)(row0 - CN) * CD; dst0 = g_Hv16 + (size_t)(row0 - CN) * CD; sc0 = 1.0f; }
    if (row1 < CN) { src1 = Hc + (size_t)row1 * CD; dst1 = g_Hc16 + (size_t)row1 * CD; sc1 = K2LOG2E; }
    else { src1 = Hv + (size_t)(row1 - CN) * CD; dst1 = g_Hv16 + (size_t)(row1 - CN) * CD; sc1 = 1.0f; }

    float4 x0 = reinterpret_cast<const float4*>(src0)[lane];
    float4 x1 = reinterpret_cast<const float4*>(src1)[lane];
    float s0 = x0.x * x0.x + x0.y * x0.y + x0.z * x0.z + x0.w * x0.w;
    float s1 = x1.x * x1.x + x1.y * x1.y + x1.z * x1.z + x1.w * x1.w;
#pragma unroll
    for (int o = 16; o > 0; o >>= 1) {
        s0 += __shfl_xor_sync(0xffffffffu, s0, o);
        s1 += __shfl_xor_sync(0xffffffffu, s1, o);
    }
    float i0 = sc0 * rsqrtf(fmaxf(s0, 1e-24f));
    float i1 = sc1 * rsqrtf(fmaxf(s1, 1e-24f));
    {
        __half2 h0 = __floats2half2_rn(x0.x * i0, x0.y * i0);
        __half2 h1 = __floats2half2_rn(x0.z * i0, x0.w * i0);
        uint2 u; u.x = *reinterpret_cast<uint32_t*>(&h0); u.y = *reinterpret_cast<uint32_t*>(&h1);
        reinterpret_cast<uint2*>(dst0)[lane] = u;
    }
    {
        __half2 h0 = __floats2half2_rn(x1.x * i1, x1.y * i1);
        __half2 h1 = __floats2half2_rn(x1.z * i1, x1.w * i1);
        uint2 u; u.x = *reinterpret_cast<uint32_t*>(&h0); u.y = *reinterpret_cast<uint32_t*>(&h1);
        reinterpret_cast<uint2*>(dst1)[lane] = u;
    }
}

// ---- smem tile loaders (512 threads) ----
__device__ __forceinline__ void load_A(uint32_t sb, int n0, int t) {
#pragma unroll
    for (int k = 0; k < 4; k++) {
        int q = t + k * NTHREADS;       // 0..2047
        int r = q >> 4;
        int c = q & 15;
        cp_async16(sb + A_OFF + r * RSTRIDE + c * 16,
                   g_Hc16 + (size_t)(n0 + r) * CD + c * 8);
    }
}
__device__ __forceinline__ void load_B(uint32_t sb, int buf, int m0, int t) {
    uint32_t base = sb + B_OFF + buf * B_BUF_BYTES;
#pragma unroll
    for (int k = 0; k < 6; k++) {
        int Q = t + k * NTHREADS;       // 0..3071
        int v = Q >> 10;
        int qq = Q & 1023;
        int r = qq >> 4;
        int c = qq & 15;
        cp_async16(base + v * B_VIEW_BYTES + r * RSTRIDE + c * 16,
                   g_Hv16 + ((size_t)v * CN + (m0 + r)) * CD + c * 8);
    }
}

// ---- kernel 2: HMMA fused GEMM, 16 warps (4n x 4m), ks-outer, 12 MMA chains/warp ----
__global__ __launch_bounds__(NTHREADS, 1) void sg_main_kernel(const float* __restrict__ S) {
    cudaGridDependencySynchronize();   // PDL edge from normalize

    extern __shared__ char smem[];
    uint32_t sb = smem_u32(smem);
    const int t = threadIdx.x;
    const int lane = t & 31;
    const int wid = t >> 5;
    const int wn = wid >> 2;     // 0..3 : 32-row group
    const int wm = wid & 3;      // 0..3 : 16-col group
    const int g = lane >> 3;
    const int lr = lane & 7;
    const uint32_t aoff = (uint32_t)(((g & 1) * 8 + lr) * RSTRIDE + (g >> 1) * 16);
    const uint32_t boff = (uint32_t)(((g >> 1) * 8 + lr) * RSTRIDE + (g & 1) * 16);

    const int job0 = (int)(((long long)blockIdx.x * TOTAL_JOBS) / gridDim.x);
    const int job1 = (int)(((long long)(blockIdx.x + 1) * TOTAL_JOBS) / gridDim.x);

    int j = job0;
    while (j < job1) {
        const int nt = j >> 7;
        const int mt0 = j & 127;
        const int jend = min(job1, (nt + 1) << 7);
        const int nTi = jend - j;
        const int n0 = nt * TM;

        __syncthreads();
        load_A(sb, n0, t);
        load_B(sb, 0, mt0 * TN, t);
        CP_COMMIT();
        if (nTi > 1) { load_B(sb, 1, (mt0 + 1) * TN, t); }
        CP_COMMIT();

        float denomAcc[CV][2][2];   // [v][mi][row-octet]
#pragma unroll
        for (int v = 0; v < CV; v++)
#pragma unroll
            for (int a = 0; a < 2; a++)
#pragma unroll
                for (int b = 0; b < 2; b++) denomAcc[v][a][b] = 0.0f;

        const int row_base = n0 + wn * 32 + (lane >> 2);
        const int col_base = wm * 16 + 2 * (lane & 3);
        const uint32_t abase = sb + A_OFF + (uint32_t)(wn * 32) * RSTRIDE + aoff;

        int buf = 0;
        for (int i = 0; i < nTi; i++) {
            if (i + 1 < nTi) CP_WAIT1(); else CP_WAIT0();
            __syncthreads();  // B(i) visible; compute(i-1) done everywhere

            int nbuf = buf + 2; if (nbuf >= 3) nbuf -= 3;
            if (i + 2 < nTi) { load_B(sb, nbuf, (mt0 + i + 2) * TN, t); CP_COMMIT(); }

            const int mt = mt0 + i;
            const int m0 = mt * TN;
            const bool diag = ((mt >> 1) == nt);
            // pre-packed (1 - S) weights: [mi][row-octet][ni] half2
            __half2 wv[2][2][2];
#pragma unroll
            for (int mi = 0; mi < 2; mi++)
#pragma unroll
                for (int d8 = 0; d8 < 2; d8++) {
                    const float* rp = S + (size_t)(row_base + mi * 16 + 8 * d8) * CN +
                                      (m0 + col_base);
#pragma unroll
                    for (int ni = 0; ni < 2; ni++) {
                        float2 x = *reinterpret_cast<const float2*>(rp + ni * 8);
                        wv[mi][d8][ni] = __floats2half2_rn(1.0f - x.x, 1.0f - x.y);
                    }
                }

            // 12 independent accumulator chains: [v][mi][ni] x 2 row-octet regs
            uint32_t acc[CV][2][2][2];
#pragma unroll
            for (int v = 0; v < CV; v++)
#pragma unroll
                for (int mi = 0; mi < 2; mi++)
#pragma unroll
                    for (int ni = 0; ni < 2; ni++) {
                        acc[v][mi][ni][0] = 0u; acc[v][mi][ni][1] = 0u;
                    }

            const uint32_t bb = sb + B_OFF + buf * B_BUF_BYTES +
                                (uint32_t)(wm * 16) * RSTRIDE + boff;
#pragma unroll
            for (int ks = 0; ks < 8; ks++) {
                uint32_t af0[4], af1[4];
                ldm4(af0, abase + ks * 32);
                ldm4(af1, abase + 16 * RSTRIDE + ks * 32);
                uint32_t bf[CV][4];
#pragma unroll
                for (int v = 0; v < CV; v++)
                    ldm4(bf[v], bb + v * B_VIEW_BYTES + ks * 32);
#pragma unroll
                for (int v = 0; v < CV; v++) {
                    mma16816h(acc[v][0][0], af0, bf[v][0], bf[v][1]);
                    mma16816h(acc[v][0][1], af0, bf[v][2], bf[v][3]);
                    mma16816h(acc[v][1][0], af1, bf[v][0], bf[v][1]);
                    mma16816h(acc[v][1][1], af1, bf[v][2], bf[v][3]);
                }
            }

            if (diag) {
                // extract positives: unique owner per diagonal element
#pragma unroll
                for (int v = 0; v < CV; v++)
#pragma unroll
                    for (int mi = 0; mi < 2; mi++)
#pragma unroll
                        for (int ni = 0; ni < 2; ni++)
#pragma unroll
                            for (int oct = 0; oct < 2; oct++) {
                                int row = row_base + mi * 16 + 8 * oct;
                                int col = m0 + col_base + ni * 8;
                                __half2 h = *reinterpret_cast<__half2*>(&acc[v][mi][ni][oct]);
                                if (row == col)
                                    g_pos[v * CN + row] = __half2float(h.x) * LN2F;
                                else if (row == col + 1)
                                    g_pos[v * CN + row] = __half2float(h.y) * LN2F;
                            }
            }

            // epilogue: acc holds log2(exp(2*sim)); denom += w * 2^acc
#pragma unroll
            for (int v = 0; v < CV; v++)
#pragma unroll
                for (int mi = 0; mi < 2; mi++) {
                    __half2 h0 = __floats2half2_rn(0.0f, 0.0f);
                    __half2 h1 = h0;
#pragma unroll
                    for (int ni = 0; ni < 2; ni++) {
                        h0 = __hfma2(wv[mi][0][ni], ex2h2(acc[v][mi][ni][0]), h0);
                        h1 = __hfma2(wv[mi][1][ni], ex2h2(acc[v][mi][ni][1]), h1);
                    }
                    float2 f0 = __half22float2(h0);
                    float2 f1 = __half22float2(h1);
                    denomAcc[v][mi][0] += f0.x + f0.y;
                    denomAcc[v][mi][1] += f1.x + f1.y;
                }

            buf++; if (buf >= 3) buf -= 3;
        }

        // flush denominators (reduce over lane&3 = distinct col quads)
#pragma unroll
        for (int v = 0; v < CV; v++)
#pragma unroll
            for (int mi = 0; mi < 2; mi++)
#pragma unroll
                for (int d8 = 0; d8 < 2; d8++) {
                    float val = denomAcc[v][mi][d8];
                    val += __shfl_xor_sync(0xffffffffu, val, 1);
                    val += __shfl_xor_sync(0xffffffffu, val, 2);
                    if ((lane & 3) == 0)
                        atomicAdd(&g_denom[v * CN + row_base + mi * 16 + 8 * d8], val);
                }
        j = jend;
    }
}

// ---- kernel 3: tiny loss reduction (__logf) + writeout (PDL) ----
#define FIN_THREADS 512
#define FIN_BLOCKS ((CV * CN) / FIN_THREADS)   // 48
__global__ __launch_bounds__(FIN_THREADS) void sg_finalize_kernel(float* __restrict__ out) {
    cudaGridDependencySynchronize();

    int i = blockIdx.x * FIN_THREADS + threadIdx.x;
    float den = fmaxf(g_denom[i], 1e-9f);
    float val = __logf(den) - g_pos[i];
#pragma unroll
    for (int o = 16; o > 0; o >>= 1) val += __shfl_xor_sync(0xffffffffu, val, o);
    __shared__ float part[FIN_THREADS / 32];
    if ((threadIdx.x & 31) == 0) part[threadIdx.x >> 5] = val;
    __syncthreads();
    if (threadIdx.x == 0) {
        float bs = 0.0f;
#pragma unroll
        for (int w = 0; w < FIN_THREADS / 32; w++) bs += part[w];
        atomicAdd(&g_loss, (double)bs);
        __threadfence();
        unsigned int done = atomicAdd(&g_done, 1u);
        if (done == FIN_BLOCKS - 1) {
            out[0] = (float)(g_loss / (double)((long long)CN * CV));
            g_done = 0u;
        }
    }
}

extern "C" void kernel_launch(void* const* d_in, const int* in_sizes, int n_in,
                              void* d_out, int out_size) {
    const float* Hc = (const float*)d_in[0];
    const float* S = (const float*)d_in[1];
    const float* Hv = (const float*)d_in[2];
    float* out = (float*)d_out;

    int nsm = 148;
    cudaDeviceGetAttribute(&nsm, cudaDevAttrMultiProcessorCount, 0);

    cudaFuncSetAttribute(sg_main_kernel, cudaFuncAttributeMaxDynamicSharedMemorySize,
                         SMEM_TOTAL);

    sg_normalize_kernel<<<TOTROWS / 16, 256>>>(Hc, Hv);

    {
        cudaLaunchConfig_t cfg = {};
        cfg.gridDim = dim3((unsigned)nsm, 1, 1);
        cfg.blockDim = dim3(NTHREADS, 1, 1);
        cfg.dynamicSmemBytes = SMEM_TOTAL;
        cfg.stream = 0;
        cudaLaunchAttribute attr[1];
        attr[0].id = cudaLaunchAttributeProgrammaticStreamSerialization;
        attr[0].val.programmaticStreamSerializationAllowed = 1;
        cfg.attrs = attr;
        cfg.numAttrs = 1;
        cudaLaunchKernelEx(&cfg, sg_main_kernel, S);
    }
    {
        cudaLaunchConfig_t cfg = {};
        cfg.gridDim = dim3(FIN_BLOCKS, 1, 1);
        cfg.blockDim = dim3(FIN_THREADS, 1, 1);
        cfg.dynamicSmemBytes = 0;
        cfg.stream = 0;
        cudaLaunchAttribute attr[1];
        attr[0].id = cudaLaunchAttributeProgrammaticStreamSerialization;
        attr[0].val.programmaticStreamSerializationAllowed = 1;
        cfg.attrs = attr;
        cfg.numAttrs = 1;
        cudaLaunchKernelEx(&cfg, sg_finalize_kernel, out);
    }
}

// round 17
// speedup vs baseline: 1.0600x; 1.0208x over previous
#include <cuda_runtime.h>
#include <cuda_fp16.h>
#include <math.h>
#include <cstdint>

#define CN 8192
#define CD 128
#define CV 3

#define TM 128            // n rows per CTA tile
#define TN 64             // m cols per tile
#define NTILES (CN / TM)  // 64
#define MTILES (CN / TN)  // 128
#define TOTAL_JOBS (NTILES * MTILES)  // 8192
#define TOTROWS ((CV + 1) * CN)       // 32768

#define RSTRIDE 272       // padded row stride (bytes): conflict-free ldmatrix
#define A_OFF 0
#define A_BYTES (TM * RSTRIDE)                 // 34816
#define B_OFF A_BYTES
#define B_VIEW_BYTES (TN * RSTRIDE)            // 17408
#define B_BUF_BYTES (CV * B_VIEW_BYTES)        // 52224
#define NBUF 3
#define SMEM_TOTAL (B_OFF + NBUF * B_BUF_BYTES)  // 191488

#define K2LOG2E 2.8853900817779268f  /* 2/ln2 : exp(2*sim) = 2^(sim*K2) */
#define LN2F 0.6931471805599453f

// ---- device scratch ----
__device__ __align__(256) __half g_Hc16[CN * CD];   // pre-scaled by 2/ln2
__device__ __align__(256) __half g_Hv16[CV * CN * CD];
__device__ __align__(256) float g_denom[CV * CN];
__device__ __align__(256) float g_pos[CV * CN];     // positives (diag), written by main
__device__ double g_loss;
__device__ unsigned int g_done;

// ---------------- helpers ----------------
__device__ __forceinline__ uint32_t smem_u32(const void* p) {
    uint32_t a;
    asm("{ .reg .u64 t; cvta.to.shared.u64 t, %1; cvt.u32.u64 %0, t; }" : "=r"(a) : "l"(p));
    return a;
}
__device__ __forceinline__ void cp_async16(uint32_t dst, const void* src) {
    asm volatile("cp.async.cg.shared.global [%0], [%1], 16;" :: "r"(dst), "l"(src));
}
#define CP_COMMIT() asm volatile("cp.async.commit_group;" ::: "memory")
#define CP_WAIT0()  asm volatile("cp.async.wait_group 0;" ::: "memory")
#define CP_WAIT1()  asm volatile("cp.async.wait_group 1;" ::: "memory")

__device__ __forceinline__ void ldm4(uint32_t* r, uint32_t a) {
    asm volatile("ldmatrix.sync.aligned.m8n8.x4.shared.b16 {%0,%1,%2,%3}, [%4];"
                 : "=r"(r[0]), "=r"(r[1]), "=r"(r[2]), "=r"(r[3]) : "r"(a));
}
__device__ __forceinline__ void mma16816h(uint32_t* c, const uint32_t* a, uint32_t b0, uint32_t b1) {
    asm volatile(
        "mma.sync.aligned.m16n8k16.row.col.f16.f16.f16.f16 "
        "{%0,%1}, {%2,%3,%4,%5}, {%6,%7}, {%0,%1};"
        : "+r"(c[0]), "+r"(c[1])
        : "r"(a[0]), "r"(a[1]), "r"(a[2]), "r"(a[3]), "r"(b0), "r"(b1));
}
__device__ __forceinline__ __half2 ex2h2(uint32_t x) {
    uint32_t r;
    asm("ex2.approx.f16x2 %0, %1;" : "=r"(r) : "r"(x));
    return *reinterpret_cast<__half2*>(&r);
}

// ---- kernel 1: L2-normalize, 2 rows per warp (MLP=2), fused zeroing ----
// 256 threads = 8 warps x 2 rows = 16 rows/block; grid = TOTROWS/16 = 2048
__global__ __launch_bounds__(256) void sg_normalize_kernel(const float* __restrict__ Hc,
                                                           const float* __restrict__ Hv) {
    if (blockIdx.x < (CV * CN) / 256) {
        g_denom[blockIdx.x * 256 + threadIdx.x] = 0.0f;
        if (blockIdx.x == 0 && threadIdx.x == 0) { g_loss = 0.0; g_done = 0u; }
    }

    const int wid = threadIdx.x >> 5;
    const int lane = threadIdx.x & 31;
    const int row0 = blockIdx.x * 16 + wid * 2;
    const int row1 = row0 + 1;

    const float* src0; __half* dst0; float sc0;
    const float* src1; __half* dst1; float sc1;
    if (row0 < CN) { src0 = Hc + (size_t)row0 * CD; dst0 = g_Hc16 + (size_t)row0 * CD; sc0 = K2LOG2E; }
    else { src0 = Hv + (size_t)(row0 - CN) * CD; dst0 = g_Hv16 + (size_t)(row0 - CN) * CD; sc0 = 1.0f; }
    if (row1 < CN) { src1 = Hc + (size_t)row1 * CD; dst1 = g_Hc16 + (size_t)row1 * CD; sc1 = K2LOG2E; }
    else { src1 = Hv + (size_t)(row1 - CN) * CD; dst1 = g_Hv16 + (size_t)(row1 - CN) * CD; sc1 = 1.0f; }

    float4 x0 = reinterpret_cast<const float4*>(src0)[lane];
    float4 x1 = reinterpret_cast<const float4*>(src1)[lane];
    float s0 = x0.x * x0.x + x0.y * x0.y + x0.z * x0.z + x0.w * x0.w;
    float s1 = x1.x * x1.x + x1.y * x1.y + x1.z * x1.z + x1.w * x1.w;
#pragma unroll
    for (int o = 16; o > 0; o >>= 1) {
        s0 += __shfl_xor_sync(0xffffffffu, s0, o);
        s1 += __shfl_xor_sync(0xffffffffu, s1, o);
    }
    float i0 = sc0 / fmaxf(sqrtf(s0), 1e-12f);
    float i1 = sc1 / fmaxf(sqrtf(s1), 1e-12f);
    {
        __half2 h0 = __floats2half2_rn(x0.x * i0, x0.y * i0);
        __half2 h1 = __floats2half2_rn(x0.z * i0, x0.w * i0);
        uint2 u; u.x = *reinterpret_cast<uint32_t*>(&h0); u.y = *reinterpret_cast<uint32_t*>(&h1);
        reinterpret_cast<uint2*>(dst0)[lane] = u;
    }
    {
        __half2 h0 = __floats2half2_rn(x1.x * i1, x1.y * i1);
        __half2 h1 = __floats2half2_rn(x1.z * i1, x1.w * i1);
        uint2 u; u.x = *reinterpret_cast<uint32_t*>(&h0); u.y = *reinterpret_cast<uint32_t*>(&h1);
        reinterpret_cast<uint2*>(dst1)[lane] = u;
    }
}

// ---- smem tile loaders ----
__device__ __forceinline__ void load_A(uint32_t sb, int n0, int t) {
#pragma unroll
    for (int k = 0; k < 8; k++) {
        int q = t + k * 256;
        int r = q >> 4;
        int c = q & 15;
        cp_async16(sb + A_OFF + r * RSTRIDE + c * 16,
                   g_Hc16 + (size_t)(n0 + r) * CD + c * 8);
    }
}
__device__ __forceinline__ void load_B(uint32_t sb, int buf, int m0, int t) {
    uint32_t base = sb + B_OFF + buf * B_BUF_BYTES;
#pragma unroll
    for (int k = 0; k < 12; k++) {
        int Q = t + k * 256;
        int v = Q >> 10;
        int qq = Q & 1023;
        int r = qq >> 4;
        int c = qq & 15;
        cp_async16(base + v * B_VIEW_BYTES + r * RSTRIDE + c * 16,
                   g_Hv16 + ((size_t)v * CN + (m0 + r)) * CD + c * 8);
    }
}

// ---- kernel 2: HMMA(f16-acc) fused GEMM + exp + weighted denom + diag positives ----
__global__ __launch_bounds__(256, 1) void sg_main_kernel(const float* __restrict__ S) {
    // PDL: grid may launch while normalize is still draining; wait before reading
    cudaGridDependencySynchronize();

    extern __shared__ char smem[];
    uint32_t sb = smem_u32(smem);
    const int t = threadIdx.x;
    const int lane = t & 31;
    const int wid = t >> 5;
    const int wn = wid >> 1;     // 0..3 : n quarter
    const int wm = wid & 1;      // 0..1 : m half
    const int g = lane >> 3;
    const int lr = lane & 7;
    const uint32_t aoff = (uint32_t)(((g & 1) * 8 + lr) * RSTRIDE + (g >> 1) * 16);
    const uint32_t boff = (uint32_t)(((g >> 1) * 8 + lr) * RSTRIDE + (g & 1) * 16);

    const int job0 = (int)(((long long)blockIdx.x * TOTAL_JOBS) / gridDim.x);
    const int job1 = (int)(((long long)(blockIdx.x + 1) * TOTAL_JOBS) / gridDim.x);

    int j = job0;
    while (j < job1) {
        const int nt = j >> 7;
        const int mt0 = j & 127;
        const int jend = min(job1, (nt + 1) << 7);
        const int nTi = jend - j;
        const int n0 = nt * TM;

        __syncthreads();  // previous segment fully done before overwriting smem
        load_A(sb, n0, t);
        load_B(sb, 0, mt0 * TN, t);
        CP_COMMIT();
        if (nTi > 1) { load_B(sb, 1, (mt0 + 1) * TN, t); }
        CP_COMMIT();

        uint32_t af[8][2][4];
        float denomAcc[CV][2][2];
#pragma unroll
        for (int v = 0; v < CV; v++)
#pragma unroll
            for (int a = 0; a < 2; a++)
#pragma unroll
                for (int b = 0; b < 2; b++) denomAcc[v][a][b] = 0.0f;

        const int row_base = n0 + wn * 32 + (lane >> 2);
        const int col_base = wm * 32 + 2 * (lane & 3);

        int buf = 0;
        for (int i = 0; i < nTi; i++) {
            if (i + 1 < nTi) CP_WAIT1(); else CP_WAIT0();
            __syncthreads();  // B(i) visible; compute(i-1) done everywhere

            int nbuf = buf + 2; if (nbuf >= 3) nbuf -= 3;
            if (i + 2 < nTi) { load_B(sb, nbuf, (mt0 + i + 2) * TN, t); CP_COMMIT(); }

            if (i == 0) {
                uint32_t abase = sb + A_OFF + (uint32_t)(wn * 32) * RSTRIDE + aoff;
#pragma unroll
                for (int ks = 0; ks < 8; ks++)
#pragma unroll
                    for (int mi = 0; mi < 2; mi++)
                        ldm4(af[ks][mi], abase + mi * 16 * RSTRIDE + ks * 32);
            }

            const int mt = mt0 + i;
            const int m0 = mt * TN;
            const bool diag = ((mt >> 1) == nt);   // tile contains sim diagonal
            __half2 wv[2][2][4];  // [mi][row-octet][ni]
#pragma unroll
            for (int mi = 0; mi < 2; mi++)
#pragma unroll
                for (int d8 = 0; d8 < 2; d8++) {
                    const float* rp = S + (size_t)(row_base + mi * 16 + 8 * d8) * CN +
                                      (m0 + col_base);
#pragma unroll
                    for (int ni = 0; ni < 4; ni++) {
                        float2 x = *reinterpret_cast<const float2*>(rp + ni * 8);
                        wv[mi][d8][ni] = __floats2half2_rn(1.0f - x.x, 1.0f - x.y);
                    }
                }

#pragma unroll
            for (int v = 0; v < CV; v++) {
                uint32_t acc[2][4][2];
#pragma unroll
                for (int mi = 0; mi < 2; mi++)
#pragma unroll
                    for (int ni = 0; ni < 4; ni++) {
                        acc[mi][ni][0] = 0u; acc[mi][ni][1] = 0u;
                    }

                uint32_t bbase = sb + B_OFF + buf * B_BUF_BYTES + v * B_VIEW_BYTES +
                                 (uint32_t)(wm * 32) * RSTRIDE + boff;
#pragma unroll
                for (int ks = 0; ks < 8; ks++) {
                    uint32_t bf0[4], bf1[4];
                    ldm4(bf0, bbase + ks * 32);
                    ldm4(bf1, bbase + 16 * RSTRIDE + ks * 32);
#pragma unroll
                    for (int mi = 0; mi < 2; mi++) {
                        mma16816h(acc[mi][0], af[ks][mi], bf0[0], bf0[1]);
                        mma16816h(acc[mi][1], af[ks][mi], bf0[2], bf0[3]);
                        mma16816h(acc[mi][2], af[ks][mi], bf1[0], bf1[1]);
                        mma16816h(acc[mi][3], af[ks][mi], bf1[2], bf1[3]);
                    }
                }

                if (diag) {
                    // extract positives: unique owner per diagonal element
#pragma unroll
                    for (int mi = 0; mi < 2; mi++)
#pragma unroll
                        for (int ni = 0; ni < 4; ni++)
#pragma unroll
                            for (int oct = 0; oct < 2; oct++) {
                                int row = row_base + mi * 16 + 8 * oct;
                                int col = m0 + col_base + ni * 8;
                                __half2 h = *reinterpret_cast<__half2*>(&acc[mi][ni][oct]);
                                if (row == col)
                                    g_pos[v * CN + row] = __half2float(h.x) * LN2F;
                                else if (row == col + 1)
                                    g_pos[v * CN + row] = __half2float(h.y) * LN2F;
                            }
                }

#pragma unroll
                for (int mi = 0; mi < 2; mi++) {
                    __half2 h0 = __floats2half2_rn(0.0f, 0.0f);
                    __half2 h1 = h0;
#pragma unroll
                    for (int ni = 0; ni < 4; ni++) {
                        h0 = __hfma2(wv[mi][0][ni], ex2h2(acc[mi][ni][0]), h0);
                        h1 = __hfma2(wv[mi][1][ni], ex2h2(acc[mi][ni][1]), h1);
                    }
                    float2 f0 = __half22float2(h0);
                    float2 f1 = __half22float2(h1);
                    denomAcc[v][mi][0] += f0.x + f0.y;
                    denomAcc[v][mi][1] += f1.x + f1.y;
                }
            }
            buf++; if (buf >= 3) buf -= 3;
        }

#pragma unroll
        for (int v = 0; v < CV; v++)
#pragma unroll
            for (int mi = 0; mi < 2; mi++)
#pragma unroll
                for (int d8 = 0; d8 < 2; d8++) {
                    float val = denomAcc[v][mi][d8];
                    val += __shfl_xor_sync(0xffffffffu, val, 1);
                    val += __shfl_xor_sync(0xffffffffu, val, 2);
                    if ((lane & 3) == 0)
                        atomicAdd(&g_denom[v * CN + row_base + mi * 16 + 8 * d8], val);
                }
        j = jend;
    }
}

// ---- kernel 3: tiny loss reduction (__logf) + writeout ----
#define FIN_BLOCKS ((CV * CN) / 256)   // 96
__global__ __launch_bounds__(256) void sg_finalize_kernel(float* __restrict__ out) {
    // PDL: wait for main's denoms/positives before reading
    cudaGridDependencySynchronize();

    int i = blockIdx.x * 256 + threadIdx.x;
    float den = fmaxf(g_denom[i], 1e-9f);
    float val = __logf(den) - g_pos[i];
#pragma unroll
    for (int o = 16; o > 0; o >>= 1) val += __shfl_xor_sync(0xffffffffu, val, o);
    __shared__ float part[8];
    if ((threadIdx.x & 31) == 0) part[threadIdx.x >> 5] = val;
    __syncthreads();
    if (threadIdx.x == 0) {
        float bs = 0.0f;
#pragma unroll
        for (int w = 0; w < 8; w++) bs += part[w];
        atomicAdd(&g_loss, (double)bs);
        __threadfence();
        unsigned int done = atomicAdd(&g_done, 1u);
        if (done == FIN_BLOCKS - 1) {
            out[0] = (float)(g_loss / (double)((long long)CN * CV));
            g_done = 0u;
        }
    }
}

extern "C" void kernel_launch(void* const* d_in, const int* in_sizes, int n_in,
                              void* d_out, int out_size) {
    const float* Hc = (const float*)d_in[0];
    const float* S = (const float*)d_in[1];
    const float* Hv = (const float*)d_in[2];
    float* out = (float*)d_out;

    int nsm = 148;
    cudaDeviceGetAttribute(&nsm, cudaDevAttrMultiProcessorCount, 0);

    cudaFuncSetAttribute(sg_main_kernel, cudaFuncAttributeMaxDynamicSharedMemorySize,
                         SMEM_TOTAL);

    // kernel 1: plain launch
    sg_normalize_kernel<<<TOTROWS / 16, 256>>>(Hc, Hv);

    // kernel 2: PDL — overlap grid launch with normalize tail
    {
        cudaLaunchConfig_t cfg = {};
        cfg.gridDim = dim3((unsigned)nsm, 1, 1);
        cfg.blockDim = dim3(256, 1, 1);
        cfg.dynamicSmemBytes = SMEM_TOTAL;
        cfg.stream = 0;
        cudaLaunchAttribute attr[1];
        attr[0].id = cudaLaunchAttributeProgrammaticStreamSerialization;
        attr[0].val.programmaticStreamSerializationAllowed = 1;
        cfg.attrs = attr;
        cfg.numAttrs = 1;
        cudaLaunchKernelEx(&cfg, sg_main_kernel, S);
    }

    // kernel 3: PDL — overlap grid launch with main tail
    {
        cudaLaunchConfig_t cfg = {};
        cfg.gridDim = dim3(FIN_BLOCKS, 1, 1);
        cfg.blockDim = dim3(256, 1, 1);
        cfg.dynamicSmemBytes = 0;
        cfg.stream = 0;
        cudaLaunchAttribute attr[1];
        attr[0].id = cudaLaunchAttributeProgrammaticStreamSerialization;
        attr[0].val.programmaticStreamSerializationAllowed = 1;
        cfg.attrs = attr;
        cfg.numAttrs = 1;
        cudaLaunchKernelEx(&cfg, sg_finalize_kernel, out);
    }
}